// round 9
// baseline (speedup 1.0000x reference)
#include <cuda_runtime.h>
#include <cuda_bf16.h>
#include <mma.h>
#include <math.h>

using namespace nvcuda;

// Problem constants
#define B   32
#define C   512
#define HW  196          // 14*14
#define D   8192
#define LDK 216          // smem row stride in bf16 (208 + 8 pad)
#define BC  (B * C)      // 16384
#define LDS2 68          // stage row stride (floats)
#define STAGE_F (64 * LDS2)              // floats per batch stage
#define SMEM_DYN (4*64*LDK*2 + 4*STAGE_F*4)   // 110592 + 69632 = 180224

// ---------------- device scratch (no allocations allowed) ----------------
__device__ int   g_h[2][C];
__device__ float g_s[2][C];
__device__ float g_Yt[(size_t)D * B];           // [d][b]  (b innermost)

// split two fp32 into packed bf16x2 hi and lo words
__device__ __forceinline__ void split2(float a, float b, unsigned& h, unsigned& l) {
    __nv_bfloat16 ha = __float2bfloat16(a), hb = __float2bfloat16(b);
    __nv_bfloat16 la = __float2bfloat16(a - __bfloat162float(ha));
    __nv_bfloat16 lb = __float2bfloat16(b - __bfloat162float(hb));
    h = ((unsigned)__bfloat16_as_ushort(hb) << 16) | __bfloat16_as_ushort(ha);
    l = ((unsigned)__bfloat16_as_ushort(lb) << 16) | __bfloat16_as_ushort(la);
}

// ---------------- 1. fused: extract (h,s), zero Yt ----------------
__global__ void setup_kernel(const float* __restrict__ S1,
                             const float* __restrict__ S2) {
    int bx = blockIdx.x;
    int t  = threadIdx.x;
    if (bx < 2048) {
        // ---- extract: 2 blocks per sketch row; 4 independent loads (MLP=4) ----
        int row  = bx >> 1;
        int half = bx & 1;
        int mat = row >> 9;
        int r   = row & (C - 1);
        const float4* p = (const float4*)((mat ? S2 : S1) + (size_t)r * D) + half * 1024;
        float4 v[4];
        #pragma unroll
        for (int u = 0; u < 4; u++) v[u] = p[t + u * 256];
        int   idx = -1;
        float sg  = 0.f;
        #pragma unroll
        for (int u = 0; u < 4; u++) {
            int c = half * 4096 + 4 * (t + u * 256);
            if (fabsf(v[u].x) > 0.5f) { idx = c + 0; sg = v[u].x; }
            if (fabsf(v[u].y) > 0.5f) { idx = c + 1; sg = v[u].y; }
            if (fabsf(v[u].z) > 0.5f) { idx = c + 2; sg = v[u].z; }
            if (fabsf(v[u].w) > 0.5f) { idx = c + 3; sg = v[u].w; }
        }
        if (idx >= 0) {                          // exactly one thread (whole grid) hits per row
            g_h[mat][r] = idx;
            g_s[mat][r] = sg;
        }
        return;
    }
    // ---- zero Yt: 256 blocks x 256 thr x float4 ----
    int zb = bx - 2048;
    float4* y4 = (float4*)g_Yt;
    y4[zb * 256 + t] = make_float4(0.f, 0.f, 0.f, 0.f);
}

// ---------------- 2. Gram (bf16-split wmma), staging from x, v4 red scatter ----------------
//   G = Xh.Xh^T + Xh.Xl^T + Xl.Xh^T  (drops Xl.Xl^T, ~2^-16 relative)
__global__ __launch_bounds__(256, 1) void gram_scatter(const float* __restrict__ x) {
    int bg = blockIdx.y;                         // batch group: b = bg*4 + bi
    int ti = 0, rem = blockIdx.x;                // upper-triangular tile pair, ti <= tj
    while (rem >= 8 - ti) { rem -= 8 - ti; ti++; }
    int tj = ti + rem;
    bool diag = (ti == tj);

    extern __shared__ __align__(16) __nv_bfloat16 sm[];
    __nv_bfloat16* Ahi = sm;                     // 64 x LDK each
    __nv_bfloat16* Ali = sm + 1 * 64 * LDK;
    __nv_bfloat16* Bhj = sm + 2 * 64 * LDK;
    __nv_bfloat16* Blj = sm + 3 * 64 * LDK;
    float* stage = (float*)(sm + 4 * 64 * LDK);  // 4 x (64 x LDS2) floats
    __shared__ int   hh[256];
    __shared__ float ss[256];

    int tid  = threadIdx.x;
    int warp = tid >> 5;
    int wr   = warp >> 1;        // 0..3 (m, 16 rows)
    int wc   = warp & 1;         // 0..1 (n, 32 cols)

    int gm = ti * 64, gn = tj * 64;
    if (tid < 64) {
        hh[tid]       = g_h[0][gm + tid];        // h1 over row range
        hh[64 + tid]  = g_h[1][gn + tid];        // h2 over col range
        hh[128 + tid] = g_h[0][gn + tid];        // h1 over col range (mirror)
        hh[192 + tid] = g_h[1][gm + tid];        // h2 over row range (mirror)
        ss[tid]       = g_s[0][gm + tid];
        ss[64 + tid]  = g_s[1][gn + tid];
        ss[128 + tid] = g_s[0][gn + tid];
        ss[192 + tid] = g_s[1][gm + tid];
    }
    // zero the K-pad [196,208) once; batch iterations never overwrite it
    for (int e = tid; e < 64 * 6; e += 256) {
        int row = e / 6, c = 196 + 2 * (e % 6);
        unsigned* z0 = (unsigned*)&Ahi[row * LDK + c];
        unsigned* z1 = (unsigned*)&Ali[row * LDK + c];
        unsigned* z2 = (unsigned*)&Bhj[row * LDK + c];
        unsigned* z3 = (unsigned*)&Blj[row * LDK + c];
        *z0 = 0u; *z1 = 0u; *z2 = 0u; *z3 = 0u;
    }

    #pragma unroll 1
    for (int bi = 0; bi < 4; bi++) {
        int b = bg * 4 + bi;
        __syncthreads();                         // prev iter's tile reads done (and hh/ss/pad ready)
        // ---- stage tiles from x (fp32, L2-resident), split hi/lo in registers ----
        const float* xa = x + ((size_t)b * C + gm) * HW;
        const float* xb = x + ((size_t)b * C + gn) * HW;
        #pragma unroll 2
        for (int idx = tid; idx < 64 * 49; idx += 256) {     // 49 float4 per 196-float row
            int row = idx / 49, q = idx - row * 49;
            float4 va = *(const float4*)&xa[row * HW + 4 * q];
            unsigned h0, h1, l0, l1;
            split2(va.x, va.y, h0, l0);
            split2(va.z, va.w, h1, l1);
            *(uint2*)&Ahi[row * LDK + 4 * q] = make_uint2(h0, h1);
            *(uint2*)&Ali[row * LDK + 4 * q] = make_uint2(l0, l1);
            if (!diag) {
                float4 vb = *(const float4*)&xb[row * HW + 4 * q];
                split2(vb.x, vb.y, h0, l0);
                split2(vb.z, vb.w, h1, l1);
                *(uint2*)&Bhj[row * LDK + 4 * q] = make_uint2(h0, h1);
                *(uint2*)&Blj[row * LDK + 4 * q] = make_uint2(l0, l1);
            }
        }
        __syncthreads();

        const __nv_bfloat16* Ph = diag ? Ahi : Bhj;
        const __nv_bfloat16* Pl = diag ? Ali : Blj;

        // 2 output tiles x 3 independent product chains
        wmma::fragment<wmma::accumulator, 16, 16, 16, float> a0hh, a0hl, a0lh, a1hh, a1hl, a1lh;
        wmma::fill_fragment(a0hh, 0.f); wmma::fill_fragment(a0hl, 0.f); wmma::fill_fragment(a0lh, 0.f);
        wmma::fill_fragment(a1hh, 0.f); wmma::fill_fragment(a1hl, 0.f); wmma::fill_fragment(a1lh, 0.f);

        #pragma unroll
        for (int kc = 0; kc < 13; kc++) {
            int ko = kc * 16;
            wmma::fragment<wmma::matrix_a, 16, 16, 16, __nv_bfloat16, wmma::row_major> ah, al;
            wmma::fragment<wmma::matrix_b, 16, 16, 16, __nv_bfloat16, wmma::col_major> bh0, bh1, bl0, bl1;
            wmma::load_matrix_sync(ah,  &Ahi[(wr * 16) * LDK + ko], LDK);
            wmma::load_matrix_sync(al,  &Ali[(wr * 16) * LDK + ko], LDK);
            wmma::load_matrix_sync(bh0, &Ph[(wc * 32) * LDK + ko], LDK);
            wmma::load_matrix_sync(bh1, &Ph[(wc * 32 + 16) * LDK + ko], LDK);
            wmma::load_matrix_sync(bl0, &Pl[(wc * 32) * LDK + ko], LDK);
            wmma::load_matrix_sync(bl1, &Pl[(wc * 32 + 16) * LDK + ko], LDK);
            wmma::mma_sync(a0hh, ah, bh0, a0hh);     // all 6 independent
            wmma::mma_sync(a1hh, ah, bh1, a1hh);
            wmma::mma_sync(a0hl, ah, bl0, a0hl);
            wmma::mma_sync(a1hl, ah, bl1, a1hl);
            wmma::mma_sync(a0lh, al, bh0, a0lh);
            wmma::mma_sync(a1lh, al, bh1, a1lh);
        }
        #pragma unroll
        for (int e = 0; e < a0hh.num_elements; e++) {
            a0hh.x[e] += a0hl.x[e] + a0lh.x[e];
            a1hh.x[e] += a1hl.x[e] + a1lh.x[e];
        }

        float* st = stage + bi * STAGE_F;
        wmma::store_matrix_sync(&st[(wr * 16) * LDS2 + wc * 32],      a0hh, LDS2, wmma::mem_row_major);
        wmma::store_matrix_sync(&st[(wr * 16) * LDS2 + wc * 32 + 16], a1hh, LDS2, wmma::mem_row_major);
    }
    __syncthreads();

    // ---- scatter: one red.v4 per (pair, orientation) covering 4 batches ----
    float* Ybase = g_Yt + bg * 4;
    #pragma unroll 2
    for (int e = tid; e < 4096; e += 256) {
        int r = e >> 6, c = e & 63;
        int off = r * LDS2 + c;
        float v0 = stage[0 * STAGE_F + off];
        float v1 = stage[1 * STAGE_F + off];
        float v2 = stage[2 * STAGE_F + off];
        float v3 = stage[3 * STAGE_F + off];
        int   d1 = (hh[r] + hh[64 + c]) & (D - 1);
        float w1 = ss[r] * ss[64 + c];
        float* p1 = Ybase + (size_t)d1 * B;
        asm volatile("red.global.add.v4.f32 [%0], {%1, %2, %3, %4};"
                     :: "l"(p1), "f"(v0 * w1), "f"(v1 * w1), "f"(v2 * w1), "f"(v3 * w1)
                     : "memory");
        if (!diag) {
            int   d2 = (hh[128 + c] + hh[192 + r]) & (D - 1);
            float w2 = ss[128 + c] * ss[192 + r];
            float* p2 = Ybase + (size_t)d2 * B;
            asm volatile("red.global.add.v4.f32 [%0], {%1, %2, %3, %4};"
                         :: "l"(p2), "f"(v0 * w2), "f"(v1 * w2), "f"(v2 * w2), "f"(v3 * w2)
                         : "memory");
        }
    }
}

// ---------------- 3. signed sqrt + L2 normalize ----------------
__global__ void finalize_kernel(float* __restrict__ out) {   // 32 blocks x 256 thr
    __shared__ float ysh[D];
    __shared__ float red[8];
    int b = blockIdx.x;
    int t = threadIdx.x;
    float ssum = 0.f;
    for (int d = t; d < D; d += 256) {
        float y  = g_Yt[(size_t)d * B + b];
        float sg = (y > 0.f) ? 1.f : ((y < 0.f) ? -1.f : 0.f);
        float v  = sg * sqrtf(fabsf(y) + 1e-8f);
        ysh[d] = v;
        ssum += v * v;
    }
    #pragma unroll
    for (int o = 16; o; o >>= 1) ssum += __shfl_xor_sync(0xffffffffu, ssum, o);
    if ((t & 31) == 0) red[t >> 5] = ssum;
    __syncthreads();
    if (t < 32) {
        float v2 = (t < 8) ? red[t] : 0.f;
        #pragma unroll
        for (int o = 4; o; o >>= 1) v2 += __shfl_xor_sync(0xffffffffu, v2, o);
        if (t == 0) red[0] = v2;
    }
    __syncthreads();
    float inv = 1.f / fmaxf(sqrtf(red[0]), 1e-12f);
    for (int d = t; d < D; d += 256)
        out[(size_t)b * D + d] = ysh[d] * inv;
}

// ---------------- launcher ----------------
extern "C" void kernel_launch(void* const* d_in, const int* in_sizes, int n_in,
                              void* d_out, int out_size) {
    const float* x  = nullptr;
    const float* S1 = nullptr;
    const float* S2 = nullptr;
    for (int i = 0; i < n_in; i++) {
        if (in_sizes[i] == B * C * HW) { x = (const float*)d_in[i]; }
        else if (!S1)                  { S1 = (const float*)d_in[i]; }
        else                           { S2 = (const float*)d_in[i]; }
    }
    float* out = (float*)d_out;

    static int smem_set = 0;
    if (!smem_set) {
        cudaFuncSetAttribute(gram_scatter, cudaFuncAttributeMaxDynamicSharedMemorySize, SMEM_DYN);
        smem_set = 1;
    }

    setup_kernel   <<<2048 + 256, 256>>>(S1, S2);
    gram_scatter   <<<dim3(36, 8), 256, SMEM_DYN>>>(x);
    finalize_kernel<<<B, 256>>>(out);
}

// round 10
// speedup vs baseline: 1.3830x; 1.3830x over previous
#include <cuda_runtime.h>
#include <cuda_bf16.h>
#include <mma.h>
#include <math.h>

using namespace nvcuda;

// Problem constants
#define B   32
#define C   512
#define HW  196          // 14*14
#define D   8192
#define KP  208          // HW padded to 13*16
#define LDK 216          // smem row stride in bf16 (208 + 8 pad)
#define BC  (B * C)      // 16384
#define LDS2 68          // stage row stride (floats)
#define STAGE_F (64 * LDS2)              // floats per batch stage
#define SMEM_DYN (4*64*LDK*2 + 4*STAGE_F*4)   // 110592 + 69632 = 180224

// ---------------- device scratch (no allocations allowed) ----------------
__device__ int   g_h[2][C];
__device__ float g_s[2][C];
__device__ __align__(32) __nv_bfloat16 g_Ah[(size_t)BC * KP];  // hi part
__device__ __align__(32) __nv_bfloat16 g_Al[(size_t)BC * KP];  // lo part
__device__ float g_Yt[(size_t)D * B];           // [d][b]  (b innermost)

__device__ __forceinline__ void cp16(unsigned dst, const void* src) {
    asm volatile("cp.async.cg.shared.global [%0], [%1], 16;" :: "r"(dst), "l"(src));
}

// ---------------- 1. fused: split-pack x, extract (h,s), zero Yt ----------------
__global__ void setup_kernel(const float* __restrict__ x,
                             const float* __restrict__ S1,
                             const float* __restrict__ S2) {
    int bx = blockIdx.x;
    int t  = threadIdx.x;
    if (bx < 1024) {
        // ---- prep: 16 x-rows per block, split into bf16 hi/lo ----
        int base = bx * 16;
        for (int e = t; e < 16 * KP; e += 256) {
            int r = e / KP, k = e - r * KP;
            int bc = base + r;
            float v = (k < HW) ? x[(size_t)bc * HW + k] : 0.f;
            __nv_bfloat16 hi = __float2bfloat16(v);
            float lo = v - __bfloat162float(hi);
            g_Ah[(size_t)bc * KP + k] = hi;
            g_Al[(size_t)bc * KP + k] = __float2bfloat16(lo);
        }
        return;
    }
    if (bx < 1024 + 2048) {
        // ---- extract: 2 blocks per sketch row; 4 independent loads (MLP=4) ----
        int q    = bx - 1024;
        int row  = q >> 1;
        int half = q & 1;
        int mat = row >> 9;
        int r   = row & (C - 1);
        const float4* p = (const float4*)((mat ? S2 : S1) + (size_t)r * D) + half * 1024;
        float4 v[4];
        #pragma unroll
        for (int u = 0; u < 4; u++) v[u] = p[t + u * 256];
        int   idx = -1;
        float sg  = 0.f;
        #pragma unroll
        for (int u = 0; u < 4; u++) {
            int c = half * 4096 + 4 * (t + u * 256);
            if (fabsf(v[u].x) > 0.5f) { idx = c + 0; sg = v[u].x; }
            if (fabsf(v[u].y) > 0.5f) { idx = c + 1; sg = v[u].y; }
            if (fabsf(v[u].z) > 0.5f) { idx = c + 2; sg = v[u].z; }
            if (fabsf(v[u].w) > 0.5f) { idx = c + 3; sg = v[u].w; }
        }
        if (idx >= 0) {                          // exactly one thread (whole grid) hits per row
            g_h[mat][r] = idx;
            g_s[mat][r] = sg;
        }
        return;
    }
    // ---- zero Yt: 256 blocks x 256 thr x float4 ----
    int zb = bx - 1024 - 2048;
    float4* y4 = (float4*)g_Yt;
    y4[zb * 256 + t] = make_float4(0.f, 0.f, 0.f, 0.f);
}

// ---------------- 2. Gram (bf16-split wmma), cp.async staging, v4 red scatter ----------------
//   G = Xh.Xh^T + Xh.Xl^T + Xl.Xh^T  (drops Xl.Xl^T, ~2^-16 relative)
__global__ __launch_bounds__(256, 1) void gram_scatter() {
    int bg = blockIdx.y;                         // batch group: b = bg*4 + bi
    int ti = 0, rem = blockIdx.x;                // upper-triangular tile pair, ti <= tj
    while (rem >= 8 - ti) { rem -= 8 - ti; ti++; }
    int tj = ti + rem;
    bool diag = (ti == tj);

    extern __shared__ __align__(16) __nv_bfloat16 sm[];
    __nv_bfloat16* Ahi = sm;                     // 64 x LDK each
    __nv_bfloat16* Ali = sm + 1 * 64 * LDK;
    __nv_bfloat16* Bhj = sm + 2 * 64 * LDK;
    __nv_bfloat16* Blj = sm + 3 * 64 * LDK;
    float* stage = (float*)(sm + 4 * 64 * LDK);  // 4 x (64 x LDS2) floats
    __shared__ int   hh[256];
    __shared__ float ss[256];

    int tid  = threadIdx.x;
    int warp = tid >> 5;
    int wr   = warp >> 1;        // 0..3 (m, 16 rows)
    int wc   = warp & 1;         // 0..1 (n, 32 cols)

    unsigned sAhi = (unsigned)__cvta_generic_to_shared(Ahi);
    unsigned sAli = (unsigned)__cvta_generic_to_shared(Ali);
    unsigned sBhj = (unsigned)__cvta_generic_to_shared(Bhj);
    unsigned sBlj = (unsigned)__cvta_generic_to_shared(Blj);

    int gm = ti * 64, gn = tj * 64;
    if (tid < 64) {
        hh[tid]       = g_h[0][gm + tid];        // h1 over row range
        hh[64 + tid]  = g_h[1][gn + tid];        // h2 over col range
        hh[128 + tid] = g_h[0][gn + tid];        // h1 over col range (mirror)
        hh[192 + tid] = g_h[1][gm + tid];        // h2 over row range (mirror)
        ss[tid]       = g_s[0][gm + tid];
        ss[64 + tid]  = g_s[1][gn + tid];
        ss[128 + tid] = g_s[0][gn + tid];
        ss[192 + tid] = g_s[1][gm + tid];
    }

    #pragma unroll 1
    for (int bi = 0; bi < 4; bi++) {
        int b = bg * 4 + bi;
        __syncthreads();                         // prev iter's tile reads done (and hh/ss ready)
        // ---- stage tiles for this batch via cp.async (no register round-trip) ----
        {
            const char* sa_h = (const char*)(g_Ah + ((size_t)b * C + gm) * KP);
            const char* sa_l = (const char*)(g_Al + ((size_t)b * C + gm) * KP);
            const char* sb_h = (const char*)(g_Ah + ((size_t)b * C + gn) * KP);
            const char* sb_l = (const char*)(g_Al + ((size_t)b * C + gn) * KP);
            #pragma unroll 2
            for (int idx = tid; idx < 64 * 26; idx += 256) {
                int row = idx / 26, q = idx - row * 26;
                int so = (row * KP + q * 8) * 2;     // byte offsets
                int dof = (row * LDK + q * 8) * 2;
                cp16(sAhi + dof, sa_h + so);
                cp16(sAli + dof, sa_l + so);
                if (!diag) {
                    cp16(sBhj + dof, sb_h + so);
                    cp16(sBlj + dof, sb_l + so);
                }
            }
            asm volatile("cp.async.commit_group;");
            asm volatile("cp.async.wait_group 0;" ::: "memory");
        }
        __syncthreads();

        const __nv_bfloat16* Ph = diag ? Ahi : Bhj;
        const __nv_bfloat16* Pl = diag ? Ali : Blj;

        // 2 output tiles x 3 independent product chains
        wmma::fragment<wmma::accumulator, 16, 16, 16, float> a0hh, a0hl, a0lh, a1hh, a1hl, a1lh;
        wmma::fill_fragment(a0hh, 0.f); wmma::fill_fragment(a0hl, 0.f); wmma::fill_fragment(a0lh, 0.f);
        wmma::fill_fragment(a1hh, 0.f); wmma::fill_fragment(a1hl, 0.f); wmma::fill_fragment(a1lh, 0.f);

        #pragma unroll
        for (int kc = 0; kc < 13; kc++) {
            int ko = kc * 16;
            wmma::fragment<wmma::matrix_a, 16, 16, 16, __nv_bfloat16, wmma::row_major> ah, al;
            wmma::fragment<wmma::matrix_b, 16, 16, 16, __nv_bfloat16, wmma::col_major> bh0, bh1, bl0, bl1;
            wmma::load_matrix_sync(ah,  &Ahi[(wr * 16) * LDK + ko], LDK);
            wmma::load_matrix_sync(al,  &Ali[(wr * 16) * LDK + ko], LDK);
            wmma::load_matrix_sync(bh0, &Ph[(wc * 32) * LDK + ko], LDK);
            wmma::load_matrix_sync(bh1, &Ph[(wc * 32 + 16) * LDK + ko], LDK);
            wmma::load_matrix_sync(bl0, &Pl[(wc * 32) * LDK + ko], LDK);
            wmma::load_matrix_sync(bl1, &Pl[(wc * 32 + 16) * LDK + ko], LDK);
            wmma::mma_sync(a0hh, ah, bh0, a0hh);     // all 6 independent
            wmma::mma_sync(a1hh, ah, bh1, a1hh);
            wmma::mma_sync(a0hl, ah, bl0, a0hl);
            wmma::mma_sync(a1hl, ah, bl1, a1hl);
            wmma::mma_sync(a0lh, al, bh0, a0lh);
            wmma::mma_sync(a1lh, al, bh1, a1lh);
        }
        #pragma unroll
        for (int e = 0; e < a0hh.num_elements; e++) {
            a0hh.x[e] += a0hl.x[e] + a0lh.x[e];
            a1hh.x[e] += a1hl.x[e] + a1lh.x[e];
        }

        float* st = stage + bi * STAGE_F;
        wmma::store_matrix_sync(&st[(wr * 16) * LDS2 + wc * 32],      a0hh, LDS2, wmma::mem_row_major);
        wmma::store_matrix_sync(&st[(wr * 16) * LDS2 + wc * 32 + 16], a1hh, LDS2, wmma::mem_row_major);
    }
    __syncthreads();

    // ---- scatter: one red.v4 per (pair, orientation) covering 4 batches ----
    float* Ybase = g_Yt + bg * 4;
    #pragma unroll 2
    for (int e = tid; e < 4096; e += 256) {
        int r = e >> 6, c = e & 63;
        int off = r * LDS2 + c;
        float v0 = stage[0 * STAGE_F + off];
        float v1 = stage[1 * STAGE_F + off];
        float v2 = stage[2 * STAGE_F + off];
        float v3 = stage[3 * STAGE_F + off];
        int   d1 = (hh[r] + hh[64 + c]) & (D - 1);
        float w1 = ss[r] * ss[64 + c];
        float* p1 = Ybase + (size_t)d1 * B;
        asm volatile("red.global.add.v4.f32 [%0], {%1, %2, %3, %4};"
                     :: "l"(p1), "f"(v0 * w1), "f"(v1 * w1), "f"(v2 * w1), "f"(v3 * w1)
                     : "memory");
        if (!diag) {
            int   d2 = (hh[128 + c] + hh[192 + r]) & (D - 1);
            float w2 = ss[128 + c] * ss[192 + r];
            float* p2 = Ybase + (size_t)d2 * B;
            asm volatile("red.global.add.v4.f32 [%0], {%1, %2, %3, %4};"
                         :: "l"(p2), "f"(v0 * w2), "f"(v1 * w2), "f"(v2 * w2), "f"(v3 * w2)
                         : "memory");
        }
    }
}

// ---------------- 3. signed sqrt + L2 normalize ----------------
__global__ void finalize_kernel(float* __restrict__ out) {   // 32 blocks x 256 thr
    __shared__ float ysh[D];
    __shared__ float red[8];
    int b = blockIdx.x;
    int t = threadIdx.x;
    float ssum = 0.f;
    for (int d = t; d < D; d += 256) {
        float y  = g_Yt[(size_t)d * B + b];
        float sg = (y > 0.f) ? 1.f : ((y < 0.f) ? -1.f : 0.f);
        float v  = sg * sqrtf(fabsf(y) + 1e-8f);
        ysh[d] = v;
        ssum += v * v;
    }
    #pragma unroll
    for (int o = 16; o; o >>= 1) ssum += __shfl_xor_sync(0xffffffffu, ssum, o);
    if ((t & 31) == 0) red[t >> 5] = ssum;
    __syncthreads();
    if (t < 32) {
        float v2 = (t < 8) ? red[t] : 0.f;
        #pragma unroll
        for (int o = 4; o; o >>= 1) v2 += __shfl_xor_sync(0xffffffffu, v2, o);
        if (t == 0) red[0] = v2;
    }
    __syncthreads();
    float inv = 1.f / fmaxf(sqrtf(red[0]), 1e-12f);
    for (int d = t; d < D; d += 256)
        out[(size_t)b * D + d] = ysh[d] * inv;
}

// ---------------- launcher ----------------
extern "C" void kernel_launch(void* const* d_in, const int* in_sizes, int n_in,
                              void* d_out, int out_size) {
    const float* x  = nullptr;
    const float* S1 = nullptr;
    const float* S2 = nullptr;
    for (int i = 0; i < n_in; i++) {
        if (in_sizes[i] == B * C * HW) { x = (const float*)d_in[i]; }
        else if (!S1)                  { S1 = (const float*)d_in[i]; }
        else                           { S2 = (const float*)d_in[i]; }
    }
    float* out = (float*)d_out;

    static int smem_set = 0;
    if (!smem_set) {
        cudaFuncSetAttribute(gram_scatter, cudaFuncAttributeMaxDynamicSharedMemorySize, SMEM_DYN);
        smem_set = 1;
    }

    setup_kernel   <<<1024 + 2048 + 256, 256>>>(x, S1, S2);
    gram_scatter   <<<dim3(36, 8), 256, SMEM_DYN>>>();
    finalize_kernel<<<B, 256>>>(out);
}